// round 10
// baseline (speedup 1.0000x reference)
#include <cuda_runtime.h>

// out[s,:] = W_tok[x[s],:] + b_tok + W_pos[(S-1)-s,:] + b_pos
// S=8192, D=1024 fp32.
// R9: R7 chassis (persistent single-wave, 888 CTAs, branch-free min-clamped
// grid-stride loop -> timed 12.8us) with pipeline depth 2: W rows prefetched
// 2 stages ahead, token ids 3 ahead. Halves exposed DRAM latency per iter.
// R8 lesson applied: occupancy doesn't matter here; clean loop structure does.

constexpr int SEQ   = 8192;
constexpr int EMBED = 1024;
constexpr int VEC   = EMBED / 4;   // 256 float4 per row
constexpr int GRID  = 888;         // 148 SMs x 6 CTAs -> one wave

__global__ __launch_bounds__(256, 5)
void linear_embedding_kernel(const int* __restrict__ x,
                             const float4* __restrict__ W_tok,
                             const float4* __restrict__ b_tok,
                             const float4* __restrict__ W_pos,
                             const float4* __restrict__ b_pos,
                             float4* __restrict__ out)
{
    const int t      = threadIdx.x;
    const int stride = GRID;

    // Bias for this thread's column (zeros in practice; L2-resident).
    const float4 bt = __ldg(&b_tok[t]);
    const float4 bp = __ldg(&b_pos[t]);
    float4 b;
    b.x = bt.x + bp.x; b.y = bt.y + bp.y;
    b.z = bt.z + bp.z; b.w = bt.w + bp.w;

    int s = blockIdx.x;

    // Prologue: stages s, s+stride in flight; token ids through s+2*stride.
    const int sB = min(s + stride,     SEQ - 1);
    const int sC = min(s + 2 * stride, SEQ - 1);

    int tok0 = __ldg(&x[s]);
    int tok1 = __ldg(&x[sB]);
    int tok2 = __ldg(&x[sC]);

    float4 a0 = __ldg(&W_tok[(long long)tok0 * VEC + t]);
    float4 p0 = __ldg(&W_pos[(long long)(SEQ - 1 - s) * VEC + t]);
    float4 a1 = __ldg(&W_tok[(long long)tok1 * VEC + t]);
    float4 p1 = __ldg(&W_pos[(long long)(SEQ - 1 - sB) * VEC + t]);

    while (s < SEQ) {
        // Prefetch stage s+2*stride (clamped; harmless duplicate on tail).
        const int sc = min(s + 2 * stride, SEQ - 1);
        float4 a2 = __ldg(&W_tok[(long long)tok2 * VEC + t]);
        float4 p2 = __ldg(&W_pos[(long long)(SEQ - 1 - sc) * VEC + t]);
        // Token id 3 stages ahead.
        const int tok3 = __ldg(&x[min(s + 3 * stride, SEQ - 1)]);

        // Consume current row.
        float4 r;
        r.x = (a0.x + p0.x) + b.x;
        r.y = (a0.y + p0.y) + b.y;
        r.z = (a0.z + p0.z) + b.z;
        r.w = (a0.w + p0.w) + b.w;
        out[(long long)s * VEC + t] = r;

        // Rotate pipeline.
        s += stride;
        a0 = a1; p0 = p1;
        a1 = a2; p1 = p2;
        tok2 = tok3;
    }
}

extern "C" void kernel_launch(void* const* d_in, const int* in_sizes, int n_in,
                              void* d_out, int out_size)
{
    const int*    x     = (const int*)d_in[0];
    const float4* W_tok = (const float4*)d_in[1];
    const float4* b_tok = (const float4*)d_in[2];
    const float4* W_pos = (const float4*)d_in[3];
    const float4* b_pos = (const float4*)d_in[4];
    float4* out = (float4*)d_out;

    linear_embedding_kernel<<<GRID, 256>>>(x, W_tok, b_tok, W_pos, b_pos, out);
}

// round 11
// speedup vs baseline: 1.3137x; 1.3137x over previous
#include <cuda_runtime.h>

// out[s,:] = W_tok[x[s],:] + b_tok + W_pos[(S-1)-s,:] + b_pos
// S=8192, D=1024 fp32.
// R10: R7 chassis byte-for-byte (persistent single-wave 888 CTAs, depth-1
// pipeline -> timed 12.8us; R8/R9 showed any reg/structure change regresses).
// Single orthogonal change: output stored with st.global.cs (evict-first) so
// 32MB of never-re-read dirty lines don't churn the warm L2 read set.

constexpr int SEQ   = 8192;
constexpr int EMBED = 1024;
constexpr int VEC   = EMBED / 4;   // 256 float4 per row
constexpr int GRID  = 888;         // 148 SMs x 6 CTAs -> exactly one wave

__device__ __forceinline__ void st_stream(float4* p, float4 v) {
    asm volatile("st.global.cs.v4.f32 [%0], {%1,%2,%3,%4};"
                 :: "l"(p), "f"(v.x), "f"(v.y), "f"(v.z), "f"(v.w) : "memory");
}

__global__ __launch_bounds__(256, 6)
void linear_embedding_kernel(const int* __restrict__ x,
                             const float4* __restrict__ W_tok,
                             const float4* __restrict__ b_tok,
                             const float4* __restrict__ W_pos,
                             const float4* __restrict__ b_pos,
                             float4* __restrict__ out)
{
    const int t      = threadIdx.x;
    const int stride = GRID;

    // Bias for this thread's column (zeros in practice; L2-resident).
    const float4 bt = __ldg(&b_tok[t]);
    const float4 bp = __ldg(&b_pos[t]);
    float4 b;
    b.x = bt.x + bp.x; b.y = bt.y + bp.y;
    b.z = bt.z + bp.z; b.w = bt.w + bp.w;

    int s = blockIdx.x;

    // Pipeline prologue: token ids 2 stages ahead, rows 1 stage ahead.
    int s1 = min(s + stride, SEQ - 1);
    int tok0 = __ldg(&x[s]);
    int tok1 = __ldg(&x[s1]);

    float4 a0 = __ldg(&W_tok[(long long)tok0 * VEC + t]);
    float4 p0 = __ldg(&W_pos[(long long)(SEQ - 1 - s) * VEC + t]);

    while (s < SEQ) {
        const int s_next = s + stride;

        // Prefetch next row's data (clamped; harmless duplicate on tail).
        const int sn = min(s_next, SEQ - 1);
        float4 a1 = __ldg(&W_tok[(long long)tok1 * VEC + t]);
        float4 p1 = __ldg(&W_pos[(long long)(SEQ - 1 - sn) * VEC + t]);
        // Prefetch token id 2 stages ahead.
        const int s2 = min(s_next + stride, SEQ - 1);
        const int tok2 = __ldg(&x[s2]);

        // Consume current row (streaming store, evict-first).
        float4 r;
        r.x = (a0.x + p0.x) + b.x;
        r.y = (a0.y + p0.y) + b.y;
        r.z = (a0.z + p0.z) + b.z;
        r.w = (a0.w + p0.w) + b.w;
        st_stream(&out[(long long)s * VEC + t], r);

        // Rotate pipeline.
        s = s_next;
        a0 = a1; p0 = p1;
        tok1 = tok2;
    }
}

extern "C" void kernel_launch(void* const* d_in, const int* in_sizes, int n_in,
                              void* d_out, int out_size)
{
    const int*    x     = (const int*)d_in[0];
    const float4* W_tok = (const float4*)d_in[1];
    const float4* b_tok = (const float4*)d_in[2];
    const float4* W_pos = (const float4*)d_in[3];
    const float4* b_pos = (const float4*)d_in[4];
    float4* out = (float4*)d_out;

    linear_embedding_kernel<<<GRID, 256>>>(x, W_tok, b_tok, W_pos, b_pos, out);
}